// round 4
// baseline (speedup 1.0000x reference)
#include <cuda_runtime.h>
#include <cstdint>

// Problem shapes (fixed by the dataset)
#define ROWS      16384
#define PRED_COLS 100
#define TRUE_COLS 50
#define KK        50
#define TPB       32
#define NBLOCKS   (ROWS / TPB)   // 512

// Scratch (allocation-free per harness rules)
__device__ float        g_partials[NBLOCKS];
__device__ unsigned int g_count = 0;   // reset by last block each run -> replay-safe

__global__ __launch_bounds__(TPB) void mapk_kernel(
    const int*   __restrict__ y_pred,
    const int*   __restrict__ y_true,
    const float* __restrict__ mult,
    float*       __restrict__ out)
{
    // Four SEPARATE shared arrays -> compiler-provable non-aliasing ->
    // four independent RMW chains during bitmap build.
    // [word][lane] layout: bank = lane -> each lane owns a private bank.
    __shared__ unsigned int m0[32 * TPB];
    __shared__ unsigned int m1[32 * TPB];
    __shared__ unsigned int m2[32 * TPB];
    __shared__ unsigned int m3[32 * TPB];

    const int lane = threadIdx.x;
    const int row  = blockIdx.x * TPB + lane;

    // ---- front-batch ALL global loads (MLP ~38 hides DRAM latency) ----
    const int2* tr2 = (const int2*)(y_true + (size_t)row * TRUE_COLS);
    int2 t[25];
    #pragma unroll
    for (int j = 0; j < 25; ++j) t[j] = tr2[j];

    const int4* pr4 = (const int4*)(y_pred + (size_t)row * PRED_COLS);
    int4 p4[12];
    #pragma unroll
    for (int j = 0; j < 12; ++j) p4[j] = pr4[j];
    int2 ptail = ((const int2*)pr4)[24];   // pred indices 48, 49

    // ---- zero own column of all 4 sub-bitmaps (independent STS) ----
    #pragma unroll
    for (int w = 0; w < 32; ++w) {
        m0[w * TPB + lane] = 0u;
        m1[w * TPB + lane] = 0u;
        m2[w * TPB + lane] = 0u;
        m3[w * TPB + lane] = 0u;
    }

    // ---- build true bitmap: 4 independent chains (values < 1000 < 1024) ----
    #pragma unroll
    for (int j = 0; j < 25; ++j) {
        unsigned int a = (unsigned int)t[j].x;          // true index 2j
        unsigned int b = (unsigned int)t[j].y;          // true index 2j+1
        unsigned int wa = (a >> 5) & 31u, ba = 1u << (a & 31u);
        unsigned int wb = (b >> 5) & 31u, bb = 1u << (b & 31u);
        if ((j & 1) == 0) {
            m0[wa * TPB + lane] |= ba;                  // chain 0
            m1[wb * TPB + lane] |= bb;                  // chain 1
        } else {
            m2[wa * TPB + lane] |= ba;                  // chain 2
            m3[wb * TPB + lane] |= bb;                  // chain 3
        }
    }

    // ---- combine into m0 (32 independent OR-merges) ----
    #pragma unroll
    for (int w = 0; w < 32; ++w) {
        m0[w * TPB + lane] = m0[w * TPB + lane] | m1[w * TPB + lane]
                           | m2[w * TPB + lane] | m3[w * TPB + lane];
    }

    // ---- phase A: 50 independent membership tests -> 64-bit match mask ----
    unsigned int mlo = 0u, mhi = 0u;
    {
        int pv[KK];
        #pragma unroll
        for (int j = 0; j < 12; ++j) {
            pv[4*j+0] = p4[j].x; pv[4*j+1] = p4[j].y;
            pv[4*j+2] = p4[j].z; pv[4*j+3] = p4[j].w;
        }
        pv[48] = ptail.x; pv[49] = ptail.y;

        #pragma unroll
        for (int i = 0; i < KK; ++i) {
            unsigned int v   = (unsigned int)pv[i];
            unsigned int w   = (v >> 5) & 31u;
            unsigned int bit = (m0[w * TPB + lane] >> (v & 31u)) & 1u;
            if (i < 32) mlo |= bit << i;
            else        mhi |= bit << (i - 32);
        }
    }

    // ---- phase B: rare path (~2.5 matched preds/row on random data).
    //      dup_i only needs comparison against earlier MATCHED preds:
    //      equal values have equal membership, so an earlier duplicate of a
    //      matched pred is itself matched. ----
    const int* pr = y_pred + (size_t)row * PRED_COLS;   // L1-resident reload
    float cnt = 0.0f, score = 0.0f;
    unsigned int r = mlo;
    while (r) {
        int i = __ffs((int)r) - 1;  r &= r - 1u;
        int v = pr[i];
        bool dup = false;
        unsigned int e = mlo & ((1u << i) - 1u);
        while (e) { int j = __ffs((int)e) - 1; e &= e - 1u; dup |= (pr[j] == v); }
        if (!dup) { cnt += 1.0f; score += cnt * mult[i]; }
    }
    r = mhi;
    while (r) {
        int i2 = __ffs((int)r) - 1;  r &= r - 1u;
        int i  = i2 + 32;
        int v  = pr[i];
        bool dup = false;
        unsigned int e = mhi & ((1u << i2) - 1u);
        while (e) { int j = __ffs((int)e) - 1; e &= e - 1u; dup |= (pr[j + 32] == v); }
        unsigned int e2 = mlo;
        while (e2) { int j = __ffs((int)e2) - 1; e2 &= e2 - 1u; dup |= (pr[j] == v); }
        if (!dup) { cnt += 1.0f; score += cnt * mult[i]; }
    }

    // ---- warp reduction (deterministic) ----
    #pragma unroll
    for (int off = 16; off > 0; off >>= 1)
        score += __shfl_down_sync(0xFFFFFFFFu, score, off);

    unsigned int prev = 0u;
    if (lane == 0) {
        g_partials[blockIdx.x] = score;
        __threadfence();
        prev = atomicAdd(&g_count, 1u);
    }
    prev = __shfl_sync(0xFFFFFFFFu, prev, 0);

    // ---- last block: deterministic final reduction + counter reset ----
    if (prev == NBLOCKS - 1) {
        __threadfence();
        float v = 0.0f;
        #pragma unroll
        for (int k = 0; k < NBLOCKS / TPB; ++k)     // fixed order per lane
            v += g_partials[lane + k * TPB];
        #pragma unroll
        for (int off = 16; off > 0; off >>= 1)
            v += __shfl_down_sync(0xFFFFFFFFu, v, off);
        if (lane == 0) {
            out[0] = v * (1.0f / ((float)TRUE_COLS * (float)ROWS));
            g_count = 0;   // reset for next graph replay
        }
    }
}

extern "C" void kernel_launch(void* const* d_in, const int* in_sizes, int n_in,
                              void* d_out, int out_size)
{
    // Assign inputs by element count (robust to metadata ordering)
    const int*   y_pred = nullptr;
    const int*   y_true = nullptr;
    const float* mult   = nullptr;
    for (int i = 0; i < n_in; ++i) {
        if      (in_sizes[i] == ROWS * PRED_COLS) y_pred = (const int*)d_in[i];
        else if (in_sizes[i] == ROWS * TRUE_COLS) y_true = (const int*)d_in[i];
        else if (in_sizes[i] == KK)               mult   = (const float*)d_in[i];
    }
    float* out = (float*)d_out;

    mapk_kernel<<<NBLOCKS, TPB>>>(y_pred, y_true, mult, out);
}

// round 5
// speedup vs baseline: 1.4727x; 1.4727x over previous
#include <cuda_runtime.h>
#include <cstdint>

// Problem shapes (fixed by the dataset)
#define ROWS      16384
#define PRED_COLS 100
#define TRUE_COLS 50
#define KK        50
#define TPB       256
#define WPB       (TPB / 32)        // 8 warps = 8 rows per block
#define NBLOCKS   (ROWS / WPB)      // 2048

// Scratch (allocation-free per harness rules)
__device__ float        g_partials[NBLOCKS];
__device__ unsigned int g_count = 0;   // reset by last block -> graph-replay-safe

__global__ __launch_bounds__(TPB) void mapk_warp_kernel(
    const int*   __restrict__ y_pred,
    const int*   __restrict__ y_true,
    const float* __restrict__ mult,
    float*       __restrict__ out)
{
    __shared__ unsigned int bm[WPB][32];   // per-warp 1024-bit membership bitmap
    __shared__ float smult[64];
    __shared__ float red[WPB];
    __shared__ unsigned int s_prev;

    const int tid  = threadIdx.x;
    const int w    = tid >> 5;
    const int lane = tid & 31;
    if (tid < KK) smult[tid] = mult[tid];

    const int row = blockIdx.x * WPB + w;
    const int* __restrict__ tr = y_true + (size_t)row * TRUE_COLS;
    const int* __restrict__ pr = y_pred + (size_t)row * PRED_COLS;

    // ---- coalesced loads (sentinel -1 for invalid lanes; -1 maps to
    //      bit 1023 which trues (<1000) never set) ----
    int t0 = tr[lane];
    int t1 = (lane < TRUE_COLS - 32) ? tr[32 + lane] : -1;   // lanes 0..17
    int p0 = pr[lane];
    int p1 = (lane < KK - 32)        ? pr[32 + lane] : -1;   // lanes 0..17

    // ---- build bitmap: zero own word, then ~2 spread-address atomicOr ----
    bm[w][lane] = 0u;
    __syncwarp();
    atomicOr(&bm[w][((unsigned)t0 >> 5) & 31u], 1u << (t0 & 31));
    if (t1 >= 0)
        atomicOr(&bm[w][((unsigned)t1 >> 5) & 31u], 1u << (t1 & 31));
    __syncwarp();

    // ---- membership tests -> warp-uniform 50-bit match mask ----
    unsigned int b0 = (bm[w][((unsigned)p0 >> 5) & 31u] >> (p0 & 31)) & 1u;
    unsigned int b1 = (bm[w][((unsigned)p1 >> 5) & 31u] >> (p1 & 31)) & 1u;
    unsigned int mlo = __ballot_sync(0xFFFFFFFFu, b0 != 0u);
    unsigned int mhi = __ballot_sync(0xFFFFFFFFu, b1 != 0u);   // p1=-1 lanes give 0

    __syncthreads();   // smult visibility (uniform path)

    // ---- uniform scoring loop over ~matched bits only.
    //      dup(i): an earlier pred equal to pred[i]. (Equal values share
    //      membership, so restricting to earlier *matched* is implied.) ----
    unsigned long long m = ((unsigned long long)mhi << 32) | (unsigned long long)mlo;
    float cnt = 0.0f, score = 0.0f;
    while (m) {
        int i = __ffsll((long long)m) - 1;
        m &= m - 1ull;
        int v = __shfl_sync(0xFFFFFFFFu, (i < 32) ? p0 : p1, i & 31);
        unsigned int elo = __ballot_sync(0xFFFFFFFFu, p0 == v);
        unsigned int ehi = __ballot_sync(0xFFFFFFFFu, p1 == v);   // sentinel never equals v
        unsigned long long eq = ((unsigned long long)ehi << 32) | (unsigned long long)elo;
        bool dup = (eq & ((1ull << i) - 1ull)) != 0ull;
        if (!dup) { cnt += 1.0f; score += cnt * smult[i]; }
    }

    // ---- block reduction (score is warp-uniform; deterministic) ----
    if (lane == 0) red[w] = score;
    __syncthreads();
    if (w == 0) {
        float v = (lane < WPB) ? red[lane] : 0.0f;
        #pragma unroll
        for (int off = WPB / 2; off > 0; off >>= 1)
            v += __shfl_down_sync(0xFFFFFFFFu, v, off);
        if (lane == 0) {
            g_partials[blockIdx.x] = v;
            __threadfence();
            s_prev = atomicAdd(&g_count, 1u);
        }
    }
    __syncthreads();

    // ---- last block: deterministic final reduction + counter reset ----
    if (s_prev == NBLOCKS - 1) {
        __threadfence();
        float v = 0.0f;
        #pragma unroll
        for (int k = 0; k < NBLOCKS / TPB; ++k)   // 8 fixed-stride terms per thread
            v += g_partials[tid + k * TPB];
        #pragma unroll
        for (int off = 16; off > 0; off >>= 1)
            v += __shfl_down_sync(0xFFFFFFFFu, v, off);
        if (lane == 0) red[w] = v;
        __syncthreads();
        if (tid == 0) {
            float s = 0.0f;
            #pragma unroll
            for (int k = 0; k < WPB; ++k) s += red[k];
            out[0] = s * (1.0f / ((float)TRUE_COLS * (float)ROWS));
            g_count = 0;   // reset for next graph replay
        }
    }
}

extern "C" void kernel_launch(void* const* d_in, const int* in_sizes, int n_in,
                              void* d_out, int out_size)
{
    // Assign inputs by element count (robust to metadata ordering)
    const int*   y_pred = nullptr;
    const int*   y_true = nullptr;
    const float* mult   = nullptr;
    for (int i = 0; i < n_in; ++i) {
        if      (in_sizes[i] == ROWS * PRED_COLS) y_pred = (const int*)d_in[i];
        else if (in_sizes[i] == ROWS * TRUE_COLS) y_true = (const int*)d_in[i];
        else if (in_sizes[i] == KK)               mult   = (const float*)d_in[i];
    }
    float* out = (float*)d_out;

    mapk_warp_kernel<<<NBLOCKS, TPB>>>(y_pred, y_true, mult, out);
}